// round 8
// baseline (speedup 1.0000x reference)
#include <cuda_runtime.h>
#include <math.h>

// ---------------------------------------------------------------------------
// Multi-scale region distillation loss — ONE fused kernel.
//
// R8 geometry: 1 thread = (pixel, channel-half). Half-warp (16 lanes) = 16
// consecutive pixels; lane bit 4 selects channel half [0,C/2) vs [C/2,C).
// Combine with shfl_xor(16). This DOUBLES the grid (680 -> 1360 blocks):
// R7 post-mortem showed occupancy was grid-limited (174k threads vs 303k
// capacity), and DRAM% tracked resident threads (45% @ 55% occ).
//
// Coalescing: each LDG.32 covers 64B contiguous per half-warp (nL=2);
// queue load 8 warps x 8 LDG x 2 lines = 128 << 248. ~28 regs, 8 blocks/SM.
// ---------------------------------------------------------------------------

#define NUM_SCALES 4
#define MAXC 32            // class bins (labels >= MAXC / < 0 dropped)
#define LAB_DIM 512
#define THREADS 256
#define PX_PER_BLOCK (THREADS / 2)   // 128 pixels per block (2-way channel split)

__device__ double       g_seg[NUM_SCALES * MAXC];   // zero-init at load
__device__ float        g_cnt[NUM_SCALES * MAXC];   // zero-init at load
__device__ unsigned int g_blocks_done = 0;          // zero-init at load

struct ScaleDesc {
    const float* f;
    const float* fo;
    int C;          // channels
    int W;          // spatial width (=H)
    int HW;         // H*W
    int pixels;     // B * HW
    int block_base; // first block id of this scale
    int sub;        // LAB_DIM / H
};
struct AllDesc { ScaleDesc s[NUM_SCALES]; };

__global__ void __launch_bounds__(THREADS, 8)
msrd_main_kernel(AllDesc d, const int* __restrict__ lab,
                 const int* __restrict__ ncls_p, const int* __restrict__ nold_p,
                 float* __restrict__ out)
{
    __shared__ float s_seg[MAXC];
    __shared__ float s_cnt[MAXC];
    __shared__ int   s_is_last;
    if (threadIdx.x < MAXC) { s_seg[threadIdx.x] = 0.f; s_cnt[threadIdx.x] = 0.f; }
    __syncthreads();

    int sidx;
    if      ((int)blockIdx.x < d.s[1].block_base) sidx = 0;
    else if ((int)blockIdx.x < d.s[2].block_base) sidx = 1;
    else if ((int)blockIdx.x < d.s[3].block_base) sidx = 2;
    else                                          sidx = 3;
    const ScaleDesc sd = d.s[sidx];

    const int lblk  = (int)blockIdx.x - sd.block_base;
    const int warp  = (int)threadIdx.x >> 5;
    const int lane  = (int)threadIdx.x & 31;
    const int split = lane >> 4;                 // 0: ch [0,C/2), 1: ch [C/2,C)
    const int P     = lblk * PX_PER_BLOCK + warp * 16 + (lane & 15);
    const bool valid = (P < sd.pixels);

    float dot = 0.f, na = 0.f, nb = 0.f;
    int b = 0, p = 0;

    if (valid) {
        b = P / sd.HW;
        p = P - b * sd.HW;
        const int HW = sd.HW;
        const int Ch = sd.C >> 1;                // channels per half (128)

        const float* __restrict__ fp  =
            sd.f  + ((size_t)b * sd.C + (size_t)split * Ch) * HW + p;
        const float* __restrict__ fop =
            sd.fo + ((size_t)b * sd.C + (size_t)split * Ch) * HW + p;

        // 4 channels per batch: 8 independent LDG.32 issued before the FMAs.
        #pragma unroll 1
        for (int c = 0; c < Ch; c += 4) {
            const float a0 = fp [0 * HW];
            const float a1 = fp [1 * HW];
            const float a2 = fp [2 * HW];
            const float a3 = fp [3 * HW];
            const float o0 = fop[0 * HW];
            const float o1 = fop[1 * HW];
            const float o2 = fop[2 * HW];
            const float o3 = fop[3 * HW];
            fp  += 4 * HW;
            fop += 4 * HW;

            dot = fmaf(a0, o0, dot); na = fmaf(a0, a0, na); nb = fmaf(o0, o0, nb);
            dot = fmaf(a1, o1, dot); na = fmaf(a1, a1, na); nb = fmaf(o1, o1, nb);
            dot = fmaf(a2, o2, dot); na = fmaf(a2, a2, na); nb = fmaf(o2, o2, nb);
            dot = fmaf(a3, o3, dot); na = fmaf(a3, a3, na); nb = fmaf(o3, o3, nb);
        }
    }

    // combine the two channel halves (lane pairs differ in bit 4)
    const unsigned m = 0xffffffffu;
    dot += __shfl_xor_sync(m, dot, 16);
    na  += __shfl_xor_sync(m, na,  16);
    nb  += __shfl_xor_sync(m, nb,  16);

    if (valid && split == 0) {
        const float nf  = fmaxf(sqrtf(na), 1e-8f);
        const float nfo = fmaxf(sqrtf(nb), 1e-8f);
        const float sim = dot / (nf * nfo);

        const int h = p / sd.W;
        const int w = p - h * sd.W;
        const int l = lab[(size_t)b * LAB_DIM * LAB_DIM
                          + (size_t)(h * sd.sub) * LAB_DIM + (size_t)w * sd.sub];
        if (l >= 0 && l < MAXC) {
            atomicAdd(&s_seg[l], sim);
            atomicAdd(&s_cnt[l], 1.0f);
        }
    }

    __syncthreads();
    if (threadIdx.x < MAXC) {
        const float cs = s_cnt[threadIdx.x];
        if (cs != 0.0f) {
            atomicAdd(&g_seg[sidx * MAXC + threadIdx.x], (double)s_seg[threadIdx.x]);
            atomicAdd(&g_cnt[sidx * MAXC + threadIdx.x], cs);
        }
    }

    // ---- last-block finalize + scratch reset (threadfence reduction) ----
    __syncthreads();
    if (threadIdx.x == 0) {
        __threadfence();
        const unsigned int done = atomicAdd(&g_blocks_done, 1u);
        s_is_last = (done == gridDim.x - 1) ? 1 : 0;
    }
    __syncthreads();

    if (s_is_last) {
        __threadfence();   // make all blocks' g_seg/g_cnt visible
        if (threadIdx.x == 0) {
            const int nc = ncls_p ? *ncls_p : 21;
            const int no = nold_p ? *nold_p : 15;
            const double wts[NUM_SCALES] = {1.0, 2.0, 3.0, 4.0};
            double loss = 0.0;
            for (int s = 0; s < NUM_SCALES; ++s) {
                for (int cls = 0; cls < nc && cls < MAXC; ++cls) {
                    const float cnt = g_cnt[s * MAXC + cls];
                    if (cnt > 0.0f) {
                        const double mean = g_seg[s * MAXC + cls] / (double)cnt;
                        double factor;
                        if (cls == 0)        factor = (double)no / (double)nc;
                        else if (cls <= no)  factor = 1.0;
                        else                 factor = 0.0;
                        loss += wts[s] * factor * (1.0 - mean);
                    }
                }
            }
            *out = (float)loss;
        }

        // finalize read must complete before scratch reset
        __syncthreads();

        if (threadIdx.x == 0) g_blocks_done = 0;   // reset for next replay
        if (threadIdx.x < NUM_SCALES * MAXC / 2) {
            const int i0 = threadIdx.x * 2;
            g_seg[i0] = 0.0;  g_seg[i0 + 1] = 0.0;
            g_cnt[i0] = 0.0f; g_cnt[i0 + 1] = 0.0f;
        }
    }
}

extern "C" void kernel_launch(void* const* d_in, const int* in_sizes, int n_in,
                              void* d_out, int out_size)
{
    const int* lab = (const int*)d_in[0];
    const int B = in_sizes[0] / (LAB_DIM * LAB_DIM);

    // ---- identify feature buffers by size (order-agnostic) ----
    const float* fbuf[NUM_SCALES]  = {nullptr, nullptr, nullptr, nullptr};
    const float* fobuf[NUM_SCALES] = {nullptr, nullptr, nullptr, nullptr};
    long         szs[NUM_SCALES]   = {0, 0, 0, 0};
    int ns = 0;
    const int* scalar_ptrs[2] = {nullptr, nullptr};
    int nscalar = 0;

    for (int i = 1; i < n_in; ++i) {
        const long sz = in_sizes[i];
        if (sz <= 1) {
            if (nscalar < 2) scalar_ptrs[nscalar++] = (const int*)d_in[i];
            continue;
        }
        int j = 0;
        while (j < ns && szs[j] != sz) ++j;
        if (j == ns && ns < NUM_SCALES) {
            szs[ns] = sz; fbuf[ns] = (const float*)d_in[i]; ++ns;
        } else if (j < ns) {
            fobuf[j] = (const float*)d_in[i];
        }
    }
    // sort descending by size (scale 0 = largest)
    for (int i = 0; i < ns; ++i)
        for (int j = i + 1; j < ns; ++j)
            if (szs[j] > szs[i]) {
                long ts = szs[i]; szs[i] = szs[j]; szs[j] = ts;
                const float* tf = fbuf[i]; fbuf[i] = fbuf[j]; fbuf[j] = tf;
                const float* to = fobuf[i]; fobuf[i] = fobuf[j]; fobuf[j] = to;
            }

    // ---- build per-scale descriptors + fused grid ----
    AllDesc ad;
    int block_base = 0;
    for (int s = 0; s < NUM_SCALES; ++s) {
        const int HW_dim = 128 >> s;             // 128,64,32,16
        const int HW     = HW_dim * HW_dim;
        const int C      = (int)(szs[s] / ((long)B * HW));
        const int pixels = B * HW;
        const int nblk   = (pixels + PX_PER_BLOCK - 1) / PX_PER_BLOCK;

        ad.s[s].f          = fbuf[s];
        ad.s[s].fo         = fobuf[s];
        ad.s[s].C          = C;
        ad.s[s].W          = HW_dim;
        ad.s[s].HW         = HW;
        ad.s[s].pixels     = pixels;
        ad.s[s].block_base = block_base;
        ad.s[s].sub        = LAB_DIM / HW_dim;
        block_base += nblk;
    }

    msrd_main_kernel<<<block_base, THREADS>>>(ad, lab,
                                              scalar_ptrs[0], scalar_ptrs[1],
                                              (float*)d_out);
}